// round 4
// baseline (speedup 1.0000x reference)
#include <cuda_runtime.h>

#define N_  25000
#define KS_ 16
#define E_  400000
#define U_  48
#define UP  49
#define D_  12

typedef unsigned long long u64;

__device__ float g_h   [N_*U_];
__device__ float g_h2  [N_*U_];
__device__ float g_h3  [N_*U_];
__device__ float g_h4  [N_*U_];
__device__ float g_preh[N_*U_];
__device__ float g_w   [E_*U_];
__device__ float g_prew[E_*U_];
__device__ float g_stat[4*U_];
__device__ float g_norm[4*U_];
__device__ float g_zsum;

__device__ __forceinline__ float siluf(float v){ return __fdividef(v, 1.0f + __expf(-v)); }
__device__ __forceinline__ float sigm(float v){ return __fdividef(1.0f, 1.0f + __expf(-v)); }
__device__ __forceinline__ u64 pk2(float x, float y){
    u64 r; asm("mov.b64 %0,{%1,%2};" : "=l"(r) : "f"(x), "f"(y)); return r;
}
__device__ __forceinline__ void fma2(u64& d, u64 a, u64 b){
    asm("fma.rn.f32x2 %0,%1,%2,%0;" : "+l"(d) : "l"(a), "l"(b));
}
__device__ __forceinline__ float2 up2(u64 v){
    float2 f; asm("mov.b64 {%0,%1},%2;" : "=f"(f.x), "=f"(f.y) : "l"(v)); return f;
}

// out[c] = sum_k in[k]*Wt[k*48+c]; W loads warp-broadcast
__device__ __forceinline__ void mm48s(const float* in, const float* Wt, u64* acc){
    #pragma unroll 4
    for (int k = 0; k < U_; k++){
        float a = in[k];
        u64 pa = pk2(a, a);
        const float4* w4 = reinterpret_cast<const float4*>(Wt) + k*12;
        #pragma unroll
        for (int q = 0; q < 12; q++){
            float4 wv = w4[q];
            fma2(acc[2*q],   pa, pk2(wv.x, wv.y));
            fma2(acc[2*q+1], pa, pk2(wv.z, wv.w));
        }
    }
}

__global__ void k_init(const float* __restrict__ x, const float* __restrict__ ea,
                       const float* __restrict__ W0, const float* __restrict__ b0,
                       const float* __restrict__ eW0, const float* __restrict__ eb0){
    int total = N_*U_ + E_*U_;
    for (int idx = blockIdx.x*blockDim.x + threadIdx.x; idx < total; idx += gridDim.x*blockDim.x){
        if (idx < N_*U_){
            int r = idx / U_, c = idx - r*U_;
            g_h[idx] = siluf(fmaf(x[2*r], W0[2*c], fmaf(x[2*r+1], W0[2*c+1], b0[c])));
        } else {
            int j = idx - N_*U_;
            int r = j / U_, c = j - r*U_;
            g_w[j] = siluf(fmaf(ea[r], eW0[c], eb0[c]));
        }
    }
    if (blockIdx.x == 0 && threadIdx.x == 0) g_zsum = 0.0f;
}

// node projections h1..h4 (+ fold prev layer h update)
__global__ void __launch_bounds__(256)
k_node(int layer, int first,
       const float* __restrict__ W1, const float* __restrict__ W2,
       const float* __restrict__ W3, const float* __restrict__ W4,
       const float* __restrict__ b1, const float* __restrict__ b2,
       const float* __restrict__ b3, const float* __restrict__ b4){
    extern __shared__ float sm[];
    float* h_s = sm;                  // 64*UP
    float* Wt  = sm + 64*UP;          // 4*2304
    float* bs  = Wt + 4*U_*U_;        // 192
    int tid = threadIdx.x;
    int row0 = blockIdx.x * 64;
    int nrows = min(64, N_ - row0);

    for (int idx = tid; idx < nrows*U_; idx += 256){
        int gi = row0*U_ + idx;
        float v = g_h[gi];
        if (!first){
            int c = idx % U_;
            v += siluf(fmaf(g_preh[gi], g_norm[c], g_norm[U_+c]));
            g_h[gi] = v;
        }
        h_s[(idx/U_)*UP + (idx%U_)] = v;
    }
    for (int idx = tid; idx < 4*U_*U_; idx += 256){
        int m = idx / (U_*U_), j = idx - m*(U_*U_);
        int c = j / U_, k = j - c*U_;
        const float* src = (m==0) ? W1 : (m==1) ? W2 : (m==2) ? W3 : W4;
        Wt[m*(U_*U_) + k*U_ + c] = src[layer*U_*U_ + j];
    }
    if (tid < 4*U_){
        int m = tid / U_, c = tid - m*U_;
        const float* src = (m==0) ? b1 : (m==1) ? b2 : (m==2) ? b3 : b4;
        bs[tid] = src[layer*U_ + c];
    }
    if (blockIdx.x == 0 && tid < 4*U_) g_stat[tid] = 0.0f;
    __syncthreads();

    int r = tid & 63, m = tid >> 6;
    if (r < nrows){
        u64 acc[24];
        #pragma unroll
        for (int q = 0; q < 24; q++) acc[q] = 0ull;
        mm48s(h_s + r*UP, Wt + m*(U_*U_), acc);
        float* dp = ((m==0) ? g_preh : (m==1) ? g_h2 : (m==2) ? g_h3 : g_h4) + (row0 + r)*U_;
        #pragma unroll
        for (int q = 0; q < 24; q++){
            float2 f = up2(acc[q]);
            f.x += bs[m*U_ + 2*q];
            f.y += bs[m*U_ + 2*q + 1];
            reinterpret_cast<float2*>(dp)[q] = f;
        }
    }
}

// w update (prev layer) + gated message aggregation into preh
__global__ void __launch_bounds__(256)
k_agg(int first, const int* __restrict__ dst){
    extern __shared__ float sm[];
    float* w_s = sm;              // 256*UP
    float* msg = sm + 256*UP;     // 256*UP
    int tid = threadIdx.x;
    int node0 = blockIdx.x * 16;
    int nn = min(16, N_ - node0);
    int ne = nn * 16;
    int e0 = node0 * 16;

    for (int idx = tid; idx < ne*U_; idx += 256){
        int gi = e0*U_ + idx;
        float v = g_w[gi];
        if (!first){
            int c = idx % U_;
            v += siluf(fmaf(g_prew[gi], g_norm[2*U_+c], g_norm[3*U_+c]));
            g_w[gi] = v;
        }
        w_s[(idx/U_)*UP + (idx%U_)] = v;
    }
    __syncthreads();

    if (tid < ne){
        int d = dst[e0 + tid];
        const float4* h2r = reinterpret_cast<const float4*>(g_h2 + d*U_);
        const float* wr = w_s + tid*UP;
        float* mr = msg + tid*UP;
        #pragma unroll
        for (int q = 0; q < 12; q++){
            float4 hv = h2r[q];
            mr[4*q+0] = hv.x * sigm(wr[4*q+0]);
            mr[4*q+1] = hv.y * sigm(wr[4*q+1]);
            mr[4*q+2] = hv.z * sigm(wr[4*q+2]);
            mr[4*q+3] = hv.w * sigm(wr[4*q+3]);
        }
    }
    __syncthreads();

    int r = tid >> 4, p = tid & 15;
    if (r < nn){
        #pragma unroll
        for (int s = 0; s < 3; s++){
            int c = p + 16*s;
            float a = 0.0f;
            #pragma unroll
            for (int j = 0; j < 16; j++) a += msg[(r*16 + j)*UP + c];
            g_preh[(node0 + r)*U_ + c] += a * 0.0625f;   // deg == 16
        }
    }
}

// prew = w@We^T + be + h3[src] + h4[dst]
__global__ void __launch_bounds__(256)
k_edge(int layer, const float* __restrict__ eW, const float* __restrict__ eb,
       const int* __restrict__ dst){
    extern __shared__ float sm[];
    float* w_s = sm;               // 256*UP
    float* Wt  = sm + 256*UP;      // 2304
    float* h3s = Wt + U_*U_;       // 768
    float* ebs = h3s + 16*U_;      // 48
    int tid = threadIdx.x;
    int node0 = blockIdx.x * 16;
    int nn = min(16, N_ - node0);
    int ne = nn * 16;
    int e0 = node0 * 16;

    for (int idx = tid; idx < ne*U_; idx += 256)
        w_s[(idx/U_)*UP + (idx%U_)] = g_w[e0*U_ + idx];
    {
        const float* Wl = eW + layer*U_*U_;
        for (int idx = tid; idx < U_*U_; idx += 256){
            int c = idx / U_, k = idx - c*U_;
            Wt[k*U_ + c] = Wl[idx];
        }
    }
    for (int idx = tid; idx < nn*U_; idx += 256) h3s[idx] = g_h3[node0*U_ + idx];
    if (tid < U_) ebs[tid] = eb[layer*U_ + tid];
    __syncthreads();

    if (tid < ne){
        u64 acc[24];
        #pragma unroll
        for (int q = 0; q < 24; q++) acc[q] = 0ull;
        mm48s(w_s + tid*UP, Wt, acc);
        int d = dst[e0 + tid];
        const float4* h4r = reinterpret_cast<const float4*>(g_h4 + d*U_);
        const float* h3r = h3s + (tid >> 4)*U_;
        float* op = g_prew + (e0 + tid)*U_;
        #pragma unroll
        for (int q = 0; q < 12; q++){
            float4 hv = h4r[q];
            float2 f0 = up2(acc[2*q]);
            float2 f1 = up2(acc[2*q+1]);
            f0.x += ebs[4*q+0] + h3r[4*q+0] + hv.x;
            f0.y += ebs[4*q+1] + h3r[4*q+1] + hv.y;
            f1.x += ebs[4*q+2] + h3r[4*q+2] + hv.z;
            f1.y += ebs[4*q+3] + h3r[4*q+3] + hv.w;
            reinterpret_cast<float2*>(op)[2*q]   = f0;
            reinterpret_cast<float2*>(op)[2*q+1] = f1;
        }
    }
}

// per-channel sum/sumsq over preh and prew
__global__ void __launch_bounds__(384)
k_stats(){
    int tid = threadIdx.x;
    int g = tid % 12;
    int gt = blockIdx.x * 384 + tid;
    int stride = gridDim.x * 384;   // multiple of 12
    float4 sh  = make_float4(0,0,0,0), sh2 = make_float4(0,0,0,0);
    float4 swv = make_float4(0,0,0,0), sw2 = make_float4(0,0,0,0);
    const float4* A = reinterpret_cast<const float4*>(g_preh);
    for (int i = gt; i < N_*U_/4; i += stride){
        float4 v = A[i];
        sh.x += v.x; sh.y += v.y; sh.z += v.z; sh.w += v.w;
        sh2.x += v.x*v.x; sh2.y += v.y*v.y; sh2.z += v.z*v.z; sh2.w += v.w*v.w;
    }
    const float4* B = reinterpret_cast<const float4*>(g_prew);
    for (int i = gt; i < E_*U_/4; i += stride){
        float4 v = B[i];
        swv.x += v.x; swv.y += v.y; swv.z += v.z; swv.w += v.w;
        sw2.x += v.x*v.x; sw2.y += v.y*v.y; sw2.z += v.z*v.z; sw2.w += v.w*v.w;
    }
    __shared__ float red[12][16];
    if (tid < 192) (&red[0][0])[tid] = 0.0f;
    __syncthreads();
    atomicAdd(&red[g][0],  sh.x);  atomicAdd(&red[g][1],  sh.y);
    atomicAdd(&red[g][2],  sh.z);  atomicAdd(&red[g][3],  sh.w);
    atomicAdd(&red[g][4],  sh2.x); atomicAdd(&red[g][5],  sh2.y);
    atomicAdd(&red[g][6],  sh2.z); atomicAdd(&red[g][7],  sh2.w);
    atomicAdd(&red[g][8],  swv.x); atomicAdd(&red[g][9],  swv.y);
    atomicAdd(&red[g][10], swv.z); atomicAdd(&red[g][11], swv.w);
    atomicAdd(&red[g][12], sw2.x); atomicAdd(&red[g][13], sw2.y);
    atomicAdd(&red[g][14], sw2.z); atomicAdd(&red[g][15], sw2.w);
    __syncthreads();
    if (tid < 192){
        int gg = tid / 16, j = tid % 16;
        int which = j >> 2;
        int c = gg*4 + (j & 3);
        atomicAdd(&g_stat[which*U_ + c], red[gg][j]);
    }
}

__global__ void k_norm(int layer,
                       const float* __restrict__ vg, const float* __restrict__ vb,
                       const float* __restrict__ eg, const float* __restrict__ ebv){
    int c = threadIdx.x;
    if (c < U_){
        float m  = g_stat[c] * (1.0f/N_);
        float va = fmaxf(g_stat[U_+c]*(1.0f/N_) - m*m, 0.0f);
        float sc = vg[layer*U_ + c] * rsqrtf(va + 1e-5f);
        g_norm[c] = sc;
        g_norm[U_+c] = vb[layer*U_ + c] - m*sc;
        float mw = g_stat[2*U_+c] * (1.0f/E_);
        float vw = fmaxf(g_stat[3*U_+c]*(1.0f/E_) - mw*mw, 0.0f);
        float sw = eg[layer*U_ + c] * rsqrtf(vw + 1e-5f);
        g_norm[2*U_+c] = sw;
        g_norm[3*U_+c] = ebv[layer*U_ + c] - mw*sw;
    }
}

__global__ void __launch_bounds__(256)
k_head(const float* __restrict__ pW0, const float* __restrict__ pb0,
       const float* __restrict__ pW1, const float* __restrict__ pb1,
       const float* __restrict__ pW2, const float* __restrict__ pb2,
       const float* __restrict__ zW0, const float* __restrict__ zb0,
       const float* __restrict__ zW1, float* __restrict__ out){
    extern __shared__ float sm[];
    float* w_s = sm;                  // 256*UP
    float* W0t = sm + 256*UP;         // 2304
    float* W1t = W0t + U_*U_;
    float* Zt  = W1t + U_*U_;
    float* vec = Zt + U_*U_;          // 240: pb0|pb1|pW2|zb0|zW1
    int tid = threadIdx.x;
    int node0 = blockIdx.x * 16;
    int nn = min(16, N_ - node0);
    int ne = nn * 16;
    int e0 = node0 * 16;

    for (int idx = tid; idx < ne*U_; idx += 256){
        int gi = e0*U_ + idx;
        int c = idx % U_;
        float v = g_w[gi] + siluf(fmaf(g_prew[gi], g_norm[2*U_+c], g_norm[3*U_+c]));
        w_s[(idx/U_)*UP + c] = v;
    }
    for (int idx = tid; idx < 3*U_*U_; idx += 256){
        int m = idx / (U_*U_), j = idx - m*(U_*U_);
        int c = j / U_, k = j - c*U_;
        const float* src = (m==0) ? pW0 : (m==1) ? pW1 : zW0;
        float* dstW = (m==0) ? W0t : (m==1) ? W1t : Zt;
        dstW[k*U_ + c] = src[j];
    }
    if (tid < 240){
        int m = tid / U_, c = tid - m*U_;
        const float* src = (m==0) ? pb0 : (m==1) ? pb1 : (m==2) ? pW2 : (m==3) ? zb0 : zW1;
        vec[tid] = src[c];
    }
    __syncthreads();

    float s_val = -1e30f;
    float zdot = 0.0f;
    if (tid < ne){
        const float* in = w_s + tid*UP;
        u64 acc[24];
        #pragma unroll
        for (int q = 0; q < 24; q++) acc[q] = 0ull;
        mm48s(in, W0t, acc);
        float p[48];
        #pragma unroll
        for (int q = 0; q < 24; q++){
            float2 f = up2(acc[q]);
            p[2*q]   = siluf(f.x + vec[2*q]);
            p[2*q+1] = siluf(f.y + vec[2*q+1]);
        }
        #pragma unroll
        for (int q = 0; q < 24; q++) acc[q] = 0ull;
        mm48s(p, W1t, acc);
        float s = pb2[0];
        #pragma unroll
        for (int q = 0; q < 24; q++){
            float2 f = up2(acc[q]);
            s += siluf(f.x + vec[U_+2*q])   * vec[2*U_+2*q];
            s += siluf(f.y + vec[U_+2*q+1]) * vec[2*U_+2*q+1];
        }
        s_val = s;
        #pragma unroll
        for (int q = 0; q < 24; q++) acc[q] = 0ull;
        mm48s(in, Zt, acc);
        #pragma unroll
        for (int q = 0; q < 24; q++){
            float2 f = up2(acc[q]);
            zdot += fmaxf(f.x + vec[3*U_+2*q],   0.0f) * vec[4*U_+2*q];
            zdot += fmaxf(f.y + vec[3*U_+2*q+1], 0.0f) * vec[4*U_+2*q+1];
        }
    }

    // group-of-16 softmax (16-lane aligned)
    float mx = s_val;
    #pragma unroll
    for (int o = 8; o >= 1; o >>= 1) mx = fmaxf(mx, __shfl_xor_sync(0xffffffffu, mx, o));
    float ex = __expf(s_val - mx);
    float se = ex;
    #pragma unroll
    for (int o = 8; o >= 1; o >>= 1) se += __shfl_xor_sync(0xffffffffu, se, o);
    if (tid < ne) out[e0 + tid] = ex * __fdividef(1.0f, se);

    __shared__ float zred[8];
    float zw = zdot;
    #pragma unroll
    for (int o = 16; o >= 1; o >>= 1) zw += __shfl_xor_sync(0xffffffffu, zw, o);
    if ((tid & 31) == 0) zred[tid >> 5] = zw;
    __syncthreads();
    if (tid == 0){
        float t = 0.0f;
        #pragma unroll
        for (int i = 0; i < 8; i++) t += zred[i];
        atomicAdd(&g_zsum, t);
    }
}

__global__ void k_fin(const float* __restrict__ zb1, float* __restrict__ out){
    out[E_] = g_zsum * (1.0f/E_) + zb1[0];
}

extern "C" void kernel_launch(void* const* d_in, const int* in_sizes, int n_in,
                              void* d_out, int out_size){
    const float* x    = (const float*)d_in[0];
    const float* ea   = (const float*)d_in[1];
    const int*   ei   = (const int*)d_in[2];
    const int*   dst  = ei + E_;
    const float* vl0W = (const float*)d_in[3];
    const float* vl0b = (const float*)d_in[4];
    const float *vW[4], *vb[4];
    if (in_sizes[6] == D_*U_){                 // interleaved: vW1, vb1, vW2, vb2, ...
        for (int i = 0; i < 4; i++){ vW[i] = (const float*)d_in[5+2*i]; vb[i] = (const float*)d_in[6+2*i]; }
    } else {                                   // dict order: vW1..vW4, vb1..vb4
        for (int i = 0; i < 4; i++){ vW[i] = (const float*)d_in[5+i]; vb[i] = (const float*)d_in[9+i]; }
    }
    const float* vbn_g = (const float*)d_in[13];
    const float* vbn_b = (const float*)d_in[14];
    const float* el0W  = (const float*)d_in[15];
    const float* el0b  = (const float*)d_in[16];
    const float* eW    = (const float*)d_in[17];
    const float* eb    = (const float*)d_in[18];
    const float* ebn_g = (const float*)d_in[19];
    const float* ebn_b = (const float*)d_in[20];
    const float* pW0   = (const float*)d_in[21];
    const float* pb0   = (const float*)d_in[22];
    const float* pW1   = (const float*)d_in[23];
    const float* pb1   = (const float*)d_in[24];
    const float* pW2   = (const float*)d_in[25];
    const float* pb2   = (const float*)d_in[26];
    const float* zW0   = (const float*)d_in[27];
    const float* zb0   = (const float*)d_in[28];
    const float* zW1   = (const float*)d_in[29];
    const float* zb1   = (const float*)d_in[30];
    float* out = (float*)d_out;

    const int smNode = (64*UP + 4*U_*U_ + 4*U_) * 4;
    const int smAgg  = (2*256*UP) * 4;
    const int smEdge = (256*UP + U_*U_ + 16*U_ + U_) * 4;
    const int smHead = (256*UP + 3*U_*U_ + 5*U_) * 4;
    cudaFuncSetAttribute(k_node, cudaFuncAttributeMaxDynamicSharedMemorySize, smNode);
    cudaFuncSetAttribute(k_agg,  cudaFuncAttributeMaxDynamicSharedMemorySize, smAgg);
    cudaFuncSetAttribute(k_edge, cudaFuncAttributeMaxDynamicSharedMemorySize, smEdge);
    cudaFuncSetAttribute(k_head, cudaFuncAttributeMaxDynamicSharedMemorySize, smHead);

    const int gNode = (N_ + 63) / 64;     // 391
    const int gTile = (N_ + 15) / 16;     // 1563

    k_init<<<2048, 256>>>(x, ea, vl0W, vl0b, el0W, el0b);
    for (int L = 0; L < D_; L++){
        int first = (L == 0);
        k_node<<<gNode, 256, smNode>>>(L, first, vW[0], vW[1], vW[2], vW[3],
                                       vb[0], vb[1], vb[2], vb[3]);
        k_agg<<<gTile, 256, smAgg>>>(first, dst);
        k_edge<<<gTile, 256, smEdge>>>(L, eW, eb, dst);
        k_stats<<<160, 384>>>();
        k_norm<<<1, 64>>>(L, vbn_g, vbn_b, ebn_g, ebn_b);
    }
    k_head<<<gTile, 256, smHead>>>(pW0, pb0, pW1, pb1, pW2, pb2, zW0, zb0, zW1, out);
    k_fin<<<1, 1>>>(zb1, out);
}

// round 7
// speedup vs baseline: 2.1621x; 2.1621x over previous
#include <cuda_runtime.h>

#define N_  25000
#define E_  400000
#define U_  48
#define UP  49
#define D_  12

typedef unsigned long long u64;

__device__ float g_h   [N_*U_];
__device__ float g_h2  [N_*U_];
__device__ float g_h3  [N_*U_];
__device__ float g_h4  [N_*U_];
__device__ float g_preh[N_*U_];
__device__ float g_w   [E_*U_];
__device__ float g_prew[E_*U_];
__device__ float g_stat[4*U_];
__device__ float g_norm[4*U_];
__device__ float g_zsum;

__device__ __forceinline__ float siluf(float v){ return __fdividef(v, 1.0f + __expf(-v)); }
__device__ __forceinline__ float sigm(float v){ return __fdividef(1.0f, 1.0f + __expf(-v)); }
__device__ __forceinline__ u64 pk2(float x, float y){
    u64 r; asm("mov.b64 %0,{%1,%2};" : "=l"(r) : "f"(x), "f"(y)); return r;
}
__device__ __forceinline__ void fma2(u64& d, u64 a, u64 b){
    asm("fma.rn.f32x2 %0,%1,%2,%0;" : "+l"(d) : "l"(a), "l"(b));
}
__device__ __forceinline__ float2 up2(u64 v){
    float2 f; asm("mov.b64 {%0,%1},%2;" : "=f"(f.x), "=f"(f.y) : "l"(v)); return f;
}

// 24 outputs: acc[c] += in[k] * Wc[k*48 + c], c in [0,24). Wc must be 16B aligned.
__device__ __forceinline__ void mm24(const float* in, const float* Wc, u64* acc){
    #pragma unroll 4
    for (int k = 0; k < U_; k++){
        float a = in[k];
        u64 pa = pk2(a, a);
        const float4* w4 = reinterpret_cast<const float4*>(Wc + k*U_);
        #pragma unroll
        for (int q = 0; q < 6; q++){
            float4 wv = w4[q];
            fma2(acc[2*q],   pa, pk2(wv.x, wv.y));
            fma2(acc[2*q+1], pa, pk2(wv.z, wv.w));
        }
    }
}

__global__ void k_init(const float* __restrict__ x, const float* __restrict__ ea,
                       const float* __restrict__ W0, const float* __restrict__ b0,
                       const float* __restrict__ eW0, const float* __restrict__ eb0){
    int total = N_*U_ + E_*U_;
    for (int idx = blockIdx.x*blockDim.x + threadIdx.x; idx < total; idx += gridDim.x*blockDim.x){
        if (idx < N_*U_){
            int r = idx / U_, c = idx - r*U_;
            g_h[idx] = siluf(fmaf(x[2*r], W0[2*c], fmaf(x[2*r+1], W0[2*c+1], b0[c])));
        } else {
            int j = idx - N_*U_;
            int r = j / U_, c = j - r*U_;
            g_w[j] = siluf(fmaf(ea[r], eW0[c], eb0[c]));
        }
    }
    if (blockIdx.x == 0 && threadIdx.x == 0) g_zsum = 0.0f;
}

// ---------- node projections: h1->preh, h2, h3, h4 (+ fold prev h update) ----------
__global__ void __launch_bounds__(512, 2)
k_node(int layer, int first,
       const float* __restrict__ W1, const float* __restrict__ W2,
       const float* __restrict__ W3, const float* __restrict__ W4,
       const float* __restrict__ b1, const float* __restrict__ b2,
       const float* __restrict__ b3, const float* __restrict__ b4){
    extern __shared__ float sm[];
    float* h_s = sm;                    // 64*49
    float* Wt  = h_s + 64*UP;           // 4*2304
    float* bs  = Wt + 4*U_*U_;          // 192
    float* nrm = bs + 4*U_;             // 96
    int tid = threadIdx.x;
    int row0 = blockIdx.x * 64;
    int nrows = min(64, N_ - row0);

    if (tid < 96) nrm[tid] = g_norm[tid];
    for (int idx = tid; idx < 4*U_*U_; idx += 512){
        int m = idx / (U_*U_), j = idx - m*(U_*U_);
        int c = j / U_, k = j - c*U_;
        const float* src = (m==0) ? W1 : (m==1) ? W2 : (m==2) ? W3 : W4;
        Wt[m*(U_*U_) + k*U_ + c] = src[layer*U_*U_ + j];
    }
    if (tid < 4*U_){
        int m = tid / U_, c = tid - m*U_;
        const float* src = (m==0) ? b1 : (m==1) ? b2 : (m==2) ? b3 : b4;
        bs[tid] = src[layer*U_ + c];
    }
    if (blockIdx.x == 0 && tid < 4*U_) g_stat[tid] = 0.0f;
    __syncthreads();

    {
        const float4* hsrc = reinterpret_cast<const float4*>(g_h + row0*U_);
        const float4* psrc = reinterpret_cast<const float4*>(g_preh + row0*U_);
        float4* hdst = reinterpret_cast<float4*>(g_h + row0*U_);
        int cnt = nrows*12;
        for (int idx = tid; idx < cnt; idx += 512){
            float4 v = hsrc[idx];
            int r = idx / 12, c4 = (idx - r*12) * 4;
            if (!first){
                float4 p = psrc[idx];
                v.x += siluf(fmaf(p.x, nrm[c4],   nrm[48+c4]));
                v.y += siluf(fmaf(p.y, nrm[c4+1], nrm[48+c4+1]));
                v.z += siluf(fmaf(p.z, nrm[c4+2], nrm[48+c4+2]));
                v.w += siluf(fmaf(p.w, nrm[c4+3], nrm[48+c4+3]));
                hdst[idx] = v;
            }
            float* hp = h_s + r*UP + c4;
            hp[0]=v.x; hp[1]=v.y; hp[2]=v.z; hp[3]=v.w;
        }
    }
    __syncthreads();

    int m = tid >> 7;
    int s = tid & 127;
    int r = s >> 1;
    int half = s & 1;
    if (r < nrows){
        u64 acc[12];
        #pragma unroll
        for (int q = 0; q < 12; q++) acc[q] = 0ull;
        mm24(h_s + r*UP, Wt + m*(U_*U_) + half*24, acc);
        float* base = (m==0) ? g_preh : (m==1) ? g_h2 : (m==2) ? g_h3 : g_h4;
        float4* dp = reinterpret_cast<float4*>(base + (row0 + r)*U_ + half*24);
        const float4* bb = reinterpret_cast<const float4*>(bs + m*U_ + half*24);
        #pragma unroll
        for (int q = 0; q < 6; q++){
            float2 f0 = up2(acc[2*q]);
            float2 f1 = up2(acc[2*q+1]);
            float4 b4 = bb[q];
            float4 o;
            o.x = f0.x + b4.x; o.y = f0.y + b4.y;
            o.z = f1.x + b4.z; o.w = f1.y + b4.w;
            dp[q] = o;
        }
    }
}

// ---------- fused: w update + gated agg + edge matmul + BN stats ----------
__global__ void __launch_bounds__(512, 2)
k_fuse(int layer, int first, const float* __restrict__ eW, const float* __restrict__ eb,
       const int* __restrict__ dst){
    extern __shared__ float sm[];
    float* w_s  = sm;                   // 256*49 = 12544
    float* Wt   = w_s + 256*UP;         // 2304
    float* h3s  = Wt + U_*U_;           // 768
    float* aggs = h3s + 16*U_;          // 768
    float* ebs  = aggs + 16*U_;         // 48
    float* nrm  = ebs + U_;             // 96
    float* pst  = nrm + 96;             // 96
    float* wst  = pst + 96;             // 96
    int tid = threadIdx.x;
    int wid = tid >> 5, lane = tid & 31;
    int j = lane >> 1, half = lane & 1;
    int node0 = blockIdx.x * 16;
    int nn = min(16, N_ - node0);
    int ne = nn * 16;
    int e0 = node0 * 16;

    if (tid < 96) nrm[tid] = g_norm[96 + tid];
    if (tid < 96) pst[tid] = 0.0f;
    else if (tid < 192) wst[tid - 96] = 0.0f;
    for (int idx = tid; idx < U_*U_; idx += 512){
        int c = idx / U_, k = idx - c*U_;
        Wt[k*U_ + c] = eW[layer*U_*U_ + idx];
    }
    for (int idx = tid; idx < nn*U_; idx += 512) h3s[idx] = g_h3[node0*U_ + idx];
    if (tid < U_) ebs[tid] = eb[layer*U_ + tid];
    __syncthreads();

    // P0: update + stage w
    {
        const float4* wsrc = reinterpret_cast<const float4*>(g_w + e0*U_);
        const float4* psrc = reinterpret_cast<const float4*>(g_prew + e0*U_);
        float4* wdst = reinterpret_cast<float4*>(g_w + e0*U_);
        int cnt = ne*12;
        for (int idx = tid; idx < cnt; idx += 512){
            float4 v = wsrc[idx];
            int r = idx / 12, c4 = (idx - r*12) * 4;
            if (!first){
                float4 p = psrc[idx];
                v.x += siluf(fmaf(p.x, nrm[c4],   nrm[48+c4]));
                v.y += siluf(fmaf(p.y, nrm[c4+1], nrm[48+c4+1]));
                v.z += siluf(fmaf(p.z, nrm[c4+2], nrm[48+c4+2]));
                v.w += siluf(fmaf(p.w, nrm[c4+3], nrm[48+c4+3]));
                wdst[idx] = v;
            }
            float* wp = w_s + r*UP + c4;
            wp[0]=v.x; wp[1]=v.y; wp[2]=v.z; wp[3]=v.w;
        }
    }
    __syncthreads();

    int row = wid*16 + j;
    int e = e0 + row;
    int d = 0;

    // P1: gated message + 16-edge butterfly reduction -> aggs
    if (wid < nn){
        d = __ldg(dst + e);
        const float4* h2r = reinterpret_cast<const float4*>(g_h2 + d*U_) + half*6;
        const float* wr = w_s + row*UP + half*24;
        float4 m[6];
        #pragma unroll
        for (int q = 0; q < 6; q++){
            float4 h = h2r[q];
            m[q].x = h.x * sigm(wr[4*q+0]);
            m[q].y = h.y * sigm(wr[4*q+1]);
            m[q].z = h.z * sigm(wr[4*q+2]);
            m[q].w = h.w * sigm(wr[4*q+3]);
        }
        #pragma unroll
        for (int o = 2; o <= 16; o <<= 1){
            #pragma unroll
            for (int q = 0; q < 6; q++){
                m[q].x += __shfl_xor_sync(0xffffffffu, m[q].x, o);
                m[q].y += __shfl_xor_sync(0xffffffffu, m[q].y, o);
                m[q].z += __shfl_xor_sync(0xffffffffu, m[q].z, o);
                m[q].w += __shfl_xor_sync(0xffffffffu, m[q].w, o);
            }
        }
        if (j == 0){
            float4* ag = reinterpret_cast<float4*>(aggs + wid*U_ + half*24);
            #pragma unroll
            for (int q = 0; q < 6; q++) ag[q] = m[q];
        }
    }

    // P2: prew half-row matmul; write gmem + stash into w_s for stats
    if (wid < nn){
        u64 acc[12];
        #pragma unroll
        for (int q = 0; q < 12; q++) acc[q] = 0ull;
        mm24(w_s + row*UP, Wt + half*24, acc);
        const float4* h4r = reinterpret_cast<const float4*>(g_h4 + d*U_) + half*6;
        const float4* h3r = reinterpret_cast<const float4*>(h3s + wid*U_) + half*6;
        const float4* ebr = reinterpret_cast<const float4*>(ebs) + half*6;
        float4* op = reinterpret_cast<float4*>(g_prew + e*U_) + half*6;
        float* wsr = w_s + row*UP + half*24;
        #pragma unroll
        for (int q = 0; q < 6; q++){
            float2 f0 = up2(acc[2*q]);
            float2 f1 = up2(acc[2*q+1]);
            float4 a4 = h4r[q], a3 = h3r[q], b4 = ebr[q];
            float4 o;
            o.x = f0.x + b4.x + a3.x + a4.x;
            o.y = f0.y + b4.y + a3.y + a4.y;
            o.z = f1.x + b4.z + a3.z + a4.z;
            o.w = f1.y + b4.w + a3.w + a4.w;
            op[q] = o;
            wsr[4*q+0]=o.x; wsr[4*q+1]=o.y; wsr[4*q+2]=o.z; wsr[4*q+3]=o.w;
        }
    }
    __syncthreads();

    // P3: preh = h1 + agg/16, with node-side stats
    for (int idx = tid; idx < nn*U_; idx += 512){
        int c = idx % U_;
        float v = g_preh[node0*U_ + idx] + aggs[idx] * 0.0625f;
        g_preh[node0*U_ + idx] = v;
        atomicAdd(&pst[c], v);
        atomicAdd(&pst[48+c], v*v);
    }
    // edge-side stats over prew stashed in w_s
    if (tid < 192){
        int c = tid % U_, seg = tid / U_;
        int rend = min(seg*64 + 64, ne);
        float s = 0.0f, s2 = 0.0f;
        for (int r2 = seg*64; r2 < rend; r2++){
            float v = w_s[r2*UP + c];
            s += v; s2 += v*v;
        }
        atomicAdd(&wst[c], s);
        atomicAdd(&wst[48+c], s2);
    }
    __syncthreads();
    if (tid < 96) atomicAdd(&g_stat[tid], pst[tid]);
    else if (tid < 192) atomicAdd(&g_stat[tid], wst[tid - 96]);
}

__global__ void k_norm(int layer,
                       const float* __restrict__ vg, const float* __restrict__ vb,
                       const float* __restrict__ eg, const float* __restrict__ ebv){
    int c = threadIdx.x;
    if (c < U_){
        float m  = g_stat[c] * (1.0f/N_);
        float va = fmaxf(g_stat[U_+c]*(1.0f/N_) - m*m, 0.0f);
        float sc = vg[layer*U_ + c] * rsqrtf(va + 1e-5f);
        g_norm[c] = sc;
        g_norm[U_+c] = vb[layer*U_ + c] - m*sc;
        float mw = g_stat[2*U_+c] * (1.0f/E_);
        float vw = fmaxf(g_stat[3*U_+c]*(1.0f/E_) - mw*mw, 0.0f);
        float sw = eg[layer*U_ + c] * rsqrtf(vw + 1e-5f);
        g_norm[2*U_+c] = sw;
        g_norm[3*U_+c] = ebv[layer*U_ + c] - mw*sw;
    }
}

// ---------- head: final w update + p-MLP + group softmax + z ----------
__global__ void __launch_bounds__(512)
k_head(const float* __restrict__ pW0, const float* __restrict__ pb0,
       const float* __restrict__ pW1, const float* __restrict__ pb1,
       const float* __restrict__ pW2, const float* __restrict__ pb2,
       const float* __restrict__ zW0, const float* __restrict__ zb0,
       const float* __restrict__ zW1, float* __restrict__ out){
    extern __shared__ float sm[];
    float* w_s = sm;                    // 12544
    float* W0t = w_s + 256*UP;          // 2304
    float* W1t = W0t + U_*U_;           // 2304
    float* Zt  = W1t + U_*U_;           // 2304
    float* vec = Zt + U_*U_;            // 240
    float* nrm = vec + 240;             // 96
    float* zred = nrm + 96;             // 16
    int tid = threadIdx.x;
    int wid = tid >> 5, lane = tid & 31;
    int j = lane >> 1, half = lane & 1;
    int node0 = blockIdx.x * 16;
    int nn = min(16, N_ - node0);
    int ne = nn * 16;
    int e0 = node0 * 16;

    if (tid < 96) nrm[tid] = g_norm[96 + tid];
    for (int idx = tid; idx < 3*U_*U_; idx += 512){
        int m = idx / (U_*U_), jj = idx - m*(U_*U_);
        int c = jj / U_, k = jj - c*U_;
        const float* src = (m==0) ? pW0 : (m==1) ? pW1 : zW0;
        float* dw = (m==0) ? W0t : (m==1) ? W1t : Zt;
        dw[k*U_ + c] = src[jj];
    }
    if (tid < 240){
        int m = tid / U_, c = tid - m*U_;
        const float* src = (m==0) ? pb0 : (m==1) ? pb1 : (m==2) ? pW2 : (m==3) ? zb0 : zW1;
        vec[tid] = src[c];
    }
    __syncthreads();

    {
        const float4* wsrc = reinterpret_cast<const float4*>(g_w + e0*U_);
        const float4* psrc = reinterpret_cast<const float4*>(g_prew + e0*U_);
        int cnt = ne*12;
        for (int idx = tid; idx < cnt; idx += 512){
            float4 v = wsrc[idx];
            float4 p = psrc[idx];
            int r = idx / 12, c4 = (idx - r*12) * 4;
            v.x += siluf(fmaf(p.x, nrm[c4],   nrm[48+c4]));
            v.y += siluf(fmaf(p.y, nrm[c4+1], nrm[48+c4+1]));
            v.z += siluf(fmaf(p.z, nrm[c4+2], nrm[48+c4+2]));
            v.w += siluf(fmaf(p.w, nrm[c4+3], nrm[48+c4+3]));
            float* wp = w_s + r*UP + c4;
            wp[0]=v.x; wp[1]=v.y; wp[2]=v.z; wp[3]=v.w;
        }
    }
    __syncthreads();

    int row = wid*16 + j;
    int e = e0 + row;

    if (wid < nn){
        const float* in = w_s + row*UP;
        u64 acc[12];
        #pragma unroll
        for (int q = 0; q < 12; q++) acc[q] = 0ull;
        mm24(in, W0t + half*24, acc);
        float p[24];
        #pragma unroll
        for (int q = 0; q < 6; q++){
            float2 f0 = up2(acc[2*q]);
            float2 f1 = up2(acc[2*q+1]);
            p[4*q+0] = siluf(f0.x + vec[half*24 + 4*q+0]);
            p[4*q+1] = siluf(f0.y + vec[half*24 + 4*q+1]);
            p[4*q+2] = siluf(f1.x + vec[half*24 + 4*q+2]);
            p[4*q+3] = siluf(f1.y + vec[half*24 + 4*q+3]);
        }
        // second matmul: full 48-vec input assembled from lane pair via shfl
        #pragma unroll
        for (int q = 0; q < 12; q++) acc[q] = 0ull;
        #pragma unroll
        for (int k = 0; k < U_; k++){
            float t = p[k % 24];
            float sh = __shfl_xor_sync(0xffffffffu, t, 1);
            float a = (((k >= 24) ? 1 : 0) == half) ? t : sh;
            u64 pa = pk2(a, a);
            const float4* w4 = reinterpret_cast<const float4*>(W1t + half*24 + k*U_);
            #pragma unroll
            for (int q = 0; q < 6; q++){
                float4 wv = w4[q];
                fma2(acc[2*q],   pa, pk2(wv.x, wv.y));
                fma2(acc[2*q+1], pa, pk2(wv.z, wv.w));
            }
        }
        float sp = 0.0f;
        #pragma unroll
        for (int q = 0; q < 6; q++){
            float2 f0 = up2(acc[2*q]);
            float2 f1 = up2(acc[2*q+1]);
            sp += siluf(f0.x + vec[48+half*24+4*q+0]) * vec[96+half*24+4*q+0];
            sp += siluf(f0.y + vec[48+half*24+4*q+1]) * vec[96+half*24+4*q+1];
            sp += siluf(f1.x + vec[48+half*24+4*q+2]) * vec[96+half*24+4*q+2];
            sp += siluf(f1.y + vec[48+half*24+4*q+3]) * vec[96+half*24+4*q+3];
        }
        sp += __shfl_xor_sync(0xffffffffu, sp, 1);
        float sv = sp + __ldg(pb2);

        // z head
        #pragma unroll
        for (int q = 0; q < 12; q++) acc[q] = 0ull;
        mm24(in, Zt + half*24, acc);
        float zp = 0.0f;
        #pragma unroll
        for (int q = 0; q < 6; q++){
            float2 f0 = up2(acc[2*q]);
            float2 f1 = up2(acc[2*q+1]);
            zp += fmaxf(f0.x + vec[144+half*24+4*q+0], 0.0f) * vec[192+half*24+4*q+0];
            zp += fmaxf(f0.y + vec[144+half*24+4*q+1], 0.0f) * vec[192+half*24+4*q+1];
            zp += fmaxf(f1.x + vec[144+half*24+4*q+2], 0.0f) * vec[192+half*24+4*q+2];
            zp += fmaxf(f1.y + vec[144+half*24+4*q+3], 0.0f) * vec[192+half*24+4*q+3];
        }

        // softmax over the node's 16 edges (pairs hold identical sv)
        float mx = sv;
        #pragma unroll
        for (int o = 2; o <= 16; o <<= 1) mx = fmaxf(mx, __shfl_xor_sync(0xffffffffu, mx, o));
        float ex = __expf(sv - mx);
        float se = ex;
        #pragma unroll
        for (int o = 2; o <= 16; o <<= 1) se += __shfl_xor_sync(0xffffffffu, se, o);
        if (half == 0) out[e] = ex * __fdividef(1.0f, se);

        float zw = zp;
        #pragma unroll
        for (int o = 1; o <= 16; o <<= 1) zw += __shfl_xor_sync(0xffffffffu, zw, o);
        if (lane == 0) zred[wid] = zw;
    }
    if (wid >= nn && lane == 0) zred[wid] = 0.0f;
    __syncthreads();
    if (tid == 0){
        float t = 0.0f;
        #pragma unroll
        for (int i = 0; i < 16; i++) t += zred[i];
        atomicAdd(&g_zsum, t);
    }
}

__global__ void k_fin(const float* __restrict__ zb1, float* __restrict__ out){
    out[E_] = g_zsum * (1.0f/E_) + zb1[0];
}

extern "C" void kernel_launch(void* const* d_in, const int* in_sizes, int n_in,
                              void* d_out, int out_size){
    const float* x    = (const float*)d_in[0];
    const float* ea   = (const float*)d_in[1];
    const int*   ei   = (const int*)d_in[2];
    const int*   dst  = ei + E_;
    const float* vl0W = (const float*)d_in[3];
    const float* vl0b = (const float*)d_in[4];
    const float *vW[4], *vb[4];
    if (in_sizes[6] == D_*U_){
        for (int i = 0; i < 4; i++){ vW[i] = (const float*)d_in[5+2*i]; vb[i] = (const float*)d_in[6+2*i]; }
    } else {
        for (int i = 0; i < 4; i++){ vW[i] = (const float*)d_in[5+i]; vb[i] = (const float*)d_in[9+i]; }
    }
    const float* vbn_g = (const float*)d_in[13];
    const float* vbn_b = (const float*)d_in[14];
    const float* el0W  = (const float*)d_in[15];
    const float* el0b  = (const float*)d_in[16];
    const float* eW    = (const float*)d_in[17];
    const float* eb    = (const float*)d_in[18];
    const float* ebn_g = (const float*)d_in[19];
    const float* ebn_b = (const float*)d_in[20];
    const float* pW0   = (const float*)d_in[21];
    const float* pb0   = (const float*)d_in[22];
    const float* pW1   = (const float*)d_in[23];
    const float* pb1   = (const float*)d_in[24];
    const float* pW2   = (const float*)d_in[25];
    const float* pb2   = (const float*)d_in[26];
    const float* zW0   = (const float*)d_in[27];
    const float* zb0   = (const float*)d_in[28];
    const float* zW1   = (const float*)d_in[29];
    const float* zb1   = (const float*)d_in[30];
    float* out = (float*)d_out;

    const int smNode = (64*UP + 4*U_*U_ + 4*U_ + 96) * 4;
    const int smFuse = (256*UP + U_*U_ + 16*U_ + 16*U_ + U_ + 96 + 96 + 96) * 4;
    const int smHead = (256*UP + 3*U_*U_ + 240 + 96 + 16) * 4;
    cudaFuncSetAttribute(k_node, cudaFuncAttributeMaxDynamicSharedMemorySize, smNode);
    cudaFuncSetAttribute(k_fuse, cudaFuncAttributeMaxDynamicSharedMemorySize, smFuse);
    cudaFuncSetAttribute(k_head, cudaFuncAttributeMaxDynamicSharedMemorySize, smHead);

    const int gNode = (N_ + 63) / 64;     // 391
    const int gTile = (N_ + 15) / 16;     // 1563

    k_init<<<2048, 256>>>(x, ea, vl0W, vl0b, el0W, el0b);
    for (int L = 0; L < D_; L++){
        int first = (L == 0);
        k_node<<<gNode, 512, smNode>>>(L, first, vW[0], vW[1], vW[2], vW[3],
                                       vb[0], vb[1], vb[2], vb[3]);
        k_fuse<<<gTile, 512, smFuse>>>(L, first, eW, eb, dst);
        k_norm<<<1, 64>>>(L, vbn_g, vbn_b, ebn_g, ebn_b);
    }
    k_head<<<gTile, 512, smHead>>>(pW0, pb0, pW1, pb1, pW2, pb2, zW0, zb0, zW1, out);
    k_fin<<<1, 1>>>(zb1, out);
}